// round 14
// baseline (speedup 1.0000x reference)
#include <cuda_runtime.h>
#include <math.h>
#include <cstdint>

#define BB 64
#define TT 32
#define DD 128
#define NN 128
#define SP 132   // carry row stride (floats)
#define TS 68    // T / Sz row stride (floats)
#define NTHREADS 384

static __device__ float g_Sg[BB*NN*NN];

typedef unsigned long long u64t;

__device__ __forceinline__ float sigm(float x){ return 1.0f/(1.0f+expf(-x)); }
__device__ __forceinline__ float softplus_(float x){ return fmaxf(x,0.0f) + log1pf(expf(-fabsf(x))); }

__device__ __forceinline__ u64t pack2(float a, float b){
    u64t r; asm("mov.b64 %0, {%1,%2};" : "=l"(r) : "f"(a), "f"(b)); return r;
}
__device__ __forceinline__ void unpack2(u64t p, float& a, float& b){
    asm("mov.b64 {%0,%1}, %2;" : "=f"(a), "=f"(b) : "l"(p));
}
__device__ __forceinline__ u64t fma2_(u64t a, u64t b, u64t c){
    u64t d; asm("fma.rn.f32x2 %0, %1, %2, %3;" : "=l"(d) : "l"(a), "l"(b), "l"(c)); return d;
}
__device__ __forceinline__ uint32_t smem_u32(const void* p){
    uint32_t a;
    asm("{ .reg .u64 t; cvta.to.shared.u64 t, %1; cvt.u32.u64 %0, t; }" : "=r"(a) : "l"(p));
    return a;
}
__device__ __forceinline__ void st_peer64(uint32_t laddr, uint32_t peer, u64t v){
    uint32_t r;
    asm("mapa.shared::cluster.u32 %0, %1, %2;" : "=r"(r) : "r"(laddr), "r"(peer));
    asm volatile("st.shared::cluster.b64 [%0], %1;" :: "r"(r), "l"(v));
}
__device__ __forceinline__ void cp16(uint32_t smem_addr, const void* g){
    asm volatile("cp.async.cg.shared.global [%0], [%1], 16;" :: "r"(smem_addr), "l"(g));
}
#define CP_COMMIT() asm volatile("cp.async.commit_group;" ::: "memory")
#define CP_WAIT0()  asm volatile("cp.async.wait_group 0;"  ::: "memory")
#define CLUSTER_SYNC() do { \
    asm volatile("barrier.cluster.arrive.aligned;" ::: "memory"); \
    asm volatile("barrier.cluster.wait.aligned;"  ::: "memory"); \
} while(0)
#define BAR_GEMM() asm volatile("bar.sync 1, 256;" ::: "memory")
#define BAR_AUX()  asm volatile("bar.sync 2, 128;" ::: "memory")

// V layout (float offsets in static smem)
#define V_MU   768
#define V_Z    896
#define V_R    1024
#define V_H    1152
#define V_GZ   1280
#define V_GR   1408
#define V_GH   1536
#define V_RH   1664
#define V_XT   1792
#define V_MUN  1920
#define V_SCAL 2048
#define V_SIZE 2064

#define EPS_KICK 1.999936e-5f

// GEMM stage 1 (smem X): T[i,jl] = sum_l X[i*SP+l]*Wb[l*NN + jbg+jl]; 4 rows x 8 cols.
__device__ __forceinline__ void g_stage1s(const float* __restrict__ X,
                                          const float* __restrict__ Wb,
                                          float* __restrict__ Tsh,
                                          int rg, int cg, int c64)
{
    u64t acc[4][4];
    #pragma unroll
    for (int m=0;m<4;m++)
        #pragma unroll
        for (int q=0;q<4;q++) acc[m][q]=0ull;
    const int jbg = c64 + cg*8;
    for (int l4=0; l4<NN; l4+=4){
        float4 s4[4];
        #pragma unroll
        for (int m=0;m<4;m++)
            s4[m] = *(const float4*)&X[(size_t)(rg*4+m)*SP + l4];
        #pragma unroll
        for (int c=0;c<4;c++){
            const float4 wA = *(const float4*)&Wb[(l4+c)*NN + jbg];
            const float4 wB = *(const float4*)&Wb[(l4+c)*NN + jbg + 4];
            u64t w[4];
            w[0]=pack2(wA.x,wA.y); w[1]=pack2(wA.z,wA.w);
            w[2]=pack2(wB.x,wB.y); w[3]=pack2(wB.z,wB.w);
            #pragma unroll
            for (int m=0;m<4;m++){
                const float s = (c==0)?s4[m].x:(c==1)?s4[m].y:(c==2)?s4[m].z:s4[m].w;
                const u64t s2 = pack2(s,s);
                #pragma unroll
                for (int q=0;q<4;q++) acc[m][q] = fma2_(s2, w[q], acc[m][q]);
            }
        }
    }
    const int tb = cg*8;
    #pragma unroll
    for (int m=0;m<4;m++)
        #pragma unroll
        for (int q=0;q<4;q++)
            *(u64t*)&Tsh[(rg*4+m)*TS + tb + 2*q] = acc[m][q];
}

// GEMM stage 1 (global X, stride NN), double-buffered prefetch.
__device__ __forceinline__ void g_stage1g(const float* __restrict__ Xg,
                                          const float* __restrict__ Wb,
                                          float* __restrict__ Tsh,
                                          int rg, int cg, int c64)
{
    u64t acc[4][4];
    #pragma unroll
    for (int m=0;m<4;m++)
        #pragma unroll
        for (int q=0;q<4;q++) acc[m][q]=0ull;
    const int jbg = c64 + cg*8;
    float4 cur[4], nxt[4];
    #pragma unroll
    for (int m=0;m<4;m++)
        cur[m] = __ldcg((const float4*)&Xg[(size_t)(rg*4+m)*NN]);
    for (int l4=0; l4<NN; l4+=4){
        if (l4 < NN-4){
            #pragma unroll
            for (int m=0;m<4;m++)
                nxt[m] = __ldcg((const float4*)&Xg[(size_t)(rg*4+m)*NN + l4 + 4]);
        }
        #pragma unroll
        for (int c=0;c<4;c++){
            const float4 wA = *(const float4*)&Wb[(l4+c)*NN + jbg];
            const float4 wB = *(const float4*)&Wb[(l4+c)*NN + jbg + 4];
            u64t w[4];
            w[0]=pack2(wA.x,wA.y); w[1]=pack2(wA.z,wA.w);
            w[2]=pack2(wB.x,wB.y); w[3]=pack2(wB.z,wB.w);
            #pragma unroll
            for (int m=0;m<4;m++){
                const float s = (c==0)?cur[m].x:(c==1)?cur[m].y:(c==2)?cur[m].z:cur[m].w;
                const u64t s2 = pack2(s,s);
                #pragma unroll
                for (int q=0;q<4;q++) acc[m][q] = fma2_(s2, w[q], acc[m][q]);
            }
        }
        #pragma unroll
        for (int m=0;m<4;m++) cur[m] = nxt[m];
    }
    const int tb = cg*8;
    #pragma unroll
    for (int m=0;m<4;m++)
        #pragma unroll
        for (int q=0;q<4;q++)
            *(u64t*)&Tsh[(rg*4+m)*TS + tb + 2*q] = acc[m][q];
}

// GEMM stage 2: acc[m][..] = sum_k Wb[k*NN + ib+m] * Tsh[k, jl..]
__device__ __forceinline__ void g_stage2(const float* __restrict__ Wb,
                                         const float* __restrict__ Tsh,
                                         u64t acc[4][4], int rg, int cg)
{
    #pragma unroll
    for (int m=0;m<4;m++)
        #pragma unroll
        for (int q=0;q<4;q++) acc[m][q]=0ull;
    const int tb = cg*8, ib = rg*4;
    #pragma unroll 2
    for (int k=0;k<NN;k++){
        const float4 tA = *(const float4*)&Tsh[k*TS + tb];
        const float4 tB = *(const float4*)&Tsh[k*TS + tb + 4];
        u64t t[4];
        t[0]=pack2(tA.x,tA.y); t[1]=pack2(tA.z,tA.w);
        t[2]=pack2(tB.x,tB.y); t[3]=pack2(tB.z,tB.w);
        const float4 wa = *(const float4*)&Wb[k*NN + ib];
        #pragma unroll
        for (int m=0;m<4;m++){
            const float wm = (m==0)?wa.x:(m==1)?wa.y:(m==2)?wa.z:wa.w;
            const u64t w2 = pack2(wm, wm);
            #pragma unroll
            for (int q=0;q<4;q++) acc[m][q] = fma2_(w2, t[q], acc[m][q]);
        }
    }
}

__global__ void __launch_bounds__(NTHREADS,1) __cluster_dims__(2,1,1)
gru_kernel(const float* __restrict__ x,
           const float* __restrict__ Uz, const float* __restrict__ Wz,
           const float* __restrict__ Ur, const float* __restrict__ Wr,
           const float* __restrict__ Uh, const float* __restrict__ Wh,
           const float* __restrict__ suz, const float* __restrict__ swz,
           const float* __restrict__ sur, const float* __restrict__ swr,
           const float* __restrict__ suh, const float* __restrict__ swh,
           float* __restrict__ out_mu, float* __restrict__ out_S)
{
    extern __shared__ float sm[];
    float* Ssh  = sm;               // SP*NN : FULL carry S_p (replicated per CTA)
    float* Tsh  = Ssh + SP*NN;      // NN*TS : sandwich intermediate (own cols)
    float* Wb   = Tsh + NN*TS;      // NN*NN : staged W (full)
    float* Szsh = Wb  + NN*NN;      // NN*TS : S_z (own cols)
    __shared__ float V[V_SIZE];
    float* scal = V + V_SCAL;

    const int tid = threadIdx.x;
    const int b   = blockIdx.x >> 1;
    uint32_t rank; asm("mov.u32 %0, %%cluster_ctarank;" : "=r"(rank));
    const uint32_t peer = rank ^ 1u;
    const int c64 = (int)rank * 64;

    const bool is_gemm = (tid >= 128);
    const int wg = tid - 128;        // GEMM-local id 0..255
    const int rg = wg >> 3;          // 0..31 : rows rg*4..+3
    const int cg = wg & 7;           // 0..7  : local cols cg*8..+7
    const int ib = rg*4;
    const int jbg = c64 + cg*8;
    const int tb  = cg*8;

    const uint32_t ssh_u32 = smem_u32(Ssh);
    const uint32_t wb_u32  = smem_u32(Wb);

    float* Sgb = g_Sg + (size_t)b*NN*NN;

    for (int e = tid; e < SP*NN; e += NTHREADS) Ssh[e] = 0.f;
    if (tid < 128){
        V[tid]      = softplus_(suz[tid]);
        V[128+tid]  = softplus_(swz[tid]);
        V[256+tid]  = softplus_(sur[tid]);
        V[384+tid]  = softplus_(swr[tid]);
        V[512+tid]  = softplus_(suh[tid]);
        V[640+tid]  = softplus_(swh[tid]);
        V[V_MU+tid] = 0.f;
    }
    // initial Wz staging (all threads)
    for (int idx=tid; idx<4096; idx+=NTHREADS)
        cp16(wb_u32 + (uint32_t)idx*16, (const char*)Wz + (size_t)idx*16);
    CP_COMMIT(); CP_WAIT0();
    __syncthreads();

    for (int st = 0; st < TT; st++){
        if (!is_gemm){
            // ================= AUX warps (0-3) =================
            V[V_XT+tid] = x[(size_t)(b*TT+st)*DD + tid];
            BAR_AUX();
            // matvec z (verbatim chain)
            {
                const int j = tid; float acc = 0.f;
                #pragma unroll 32
                for (int d=0; d<DD; d++) acc += V[V_XT+d]*Uz[d*NN+j];
                #pragma unroll 32
                for (int k=0; k<NN; k++) acc += V[V_MU+k]*Wz[k*NN+j];
                const float z_ = sigm(acc);
                V[V_Z+j]  = z_;
                V[V_GZ+j] = z_*(1.f-z_);
            }
            // matvec r (verbatim chain)
            {
                const int j = tid; float acc = 0.f;
                #pragma unroll 32
                for (int d=0; d<DD; d++) acc += V[V_XT+d]*Ur[d*NN+j];
                #pragma unroll 32
                for (int k=0; k<NN; k++) acc += V[V_MU+k]*Wr[k*NN+j];
                const float r_ = sigm(acc);
                V[V_R+j]  = r_;
                V[V_GR+j] = r_*(1.f-r_);
                V[V_RH+j] = V[V_MU+j]*r_;
            }
            BAR_AUX();
            // scalar chains on 4 lanes (verbatim, branch-free trick for trS)
            if (tid < 4){
                const int which = tid;   // 0:xx 1:pp 2:trS 3:rr
                const float* src = (which==0) ? &V[V_XT] : (which==1) ? &V[V_MU]
                                 : (which==2) ? &Ssh[0]  : &V[V_RH];
                const int stride = (which==2) ? (SP+1) : 1;
                float a = 0.f;
                for (int k=0;k<NN;k++){
                    const float v = src[k*stride];
                    const float m2 = (which==2) ? 1.0f : v;
                    a += v * m2;
                }
                scal[which] = a;
            }
            // matvec h (verbatim chain)
            {
                const int j = tid; float acc = 0.f;
                #pragma unroll 32
                for (int d=0; d<DD; d++) acc += V[V_XT+d]*Uh[d*NN+j];
                #pragma unroll 32
                for (int k=0; k<NN; k++) acc += V[V_RH+k]*Wh[k*NN+j];
                const float h_ = tanhf(acc);
                V[V_H+j]  = h_;
                V[V_GH+j] = 1.f - h_*h_;
                const float mn = V[V_Z+j]*V[V_MU+j] + (1.f-V[V_Z+j])*h_;
                V[V_MUN+j] = mn;
                if (rank == 0) out_mu[(size_t)(b*TT+st)*NN + j] = mn;
            }
            __syncthreads();                       // S1
            // stage Wr while GEMM does z-epilogue
            for (int idx=tid; idx<4096; idx+=128)
                cp16(wb_u32 + (uint32_t)idx*16, (const char*)Wr + (size_t)idx*16);
            CP_COMMIT(); CP_WAIT0();
            __syncthreads();                       // S2
            // (GEMM: r-stage1 + r-stage2)
            __syncthreads();                       // S3
            // stage Wh while GEMM does r-epilogue
            for (int idx=tid; idx<4096; idx+=128)
                cp16(wb_u32 + (uint32_t)idx*16, (const char*)Wh + (size_t)idx*16);
            CP_COMMIT(); CP_WAIT0();
            CLUSTER_SYNC();                        // S4: Sg halves visible
            // trg serial chain (thread 0, pipelined loads; verbatim order)
            if (tid == 0){
                float tg=0.f;
                float va[8], vb[8];
                #pragma unroll
                for (int i=0;i<8;i++) va[i] = __ldcg(&Sgb[i*NN+i]);
                for (int g=0; g<16; g++){
                    if (g < 15){
                        #pragma unroll
                        for (int i=0;i<8;i++){
                            const int k = (g+1)*8 + i;
                            vb[i] = __ldcg(&Sgb[k*NN+k]);
                        }
                    }
                    #pragma unroll
                    for (int i=0;i<8;i++) tg += va[i];
                    #pragma unroll
                    for (int i=0;i<8;i++) va[i] = vb[i];
                }
                scal[4]=tg;
            }
            __syncthreads();                       // S5 (after GEMM h-stage2)
            // stage Wz for NEXT step while GEMM does h-epilogue
            for (int idx=tid; idx<4096; idx+=128)
                cp16(wb_u32 + (uint32_t)idx*16, (const char*)Wz + (size_t)idx*16);
            CP_COMMIT(); CP_WAIT0();
            CLUSTER_SYNC();                        // S6: carry merged
        } else {
            // ================= GEMM warps (4-11), 2 per SMSP =================
            // Z gate
            g_stage1s(Ssh, Wb, Tsh, rg, cg, c64);
            BAR_GEMM();
            u64t acc[4][4];
            g_stage2(Wb, Tsh, acc, rg, cg);
            __syncthreads();                       // S1 (z/gz/scalars ready; Wb free)
            {
                const float pp = scal[1], trS = scal[2], xx = scal[0];
                #pragma unroll
                for (int m=0;m<4;m++){
                    const int ri = ib+m;
                    const float gi = V[V_GZ+ri];
                    float o[8], out[8];
                    #pragma unroll
                    for (int q=0;q<4;q++) unpack2(acc[m][q], o[2*q], o[2*q+1]);
                    #pragma unroll
                    for (int n=0;n<8;n++){
                        const int j = jbg+n;
                        float v = o[n];
                        if (ri==j) v += pp*V[128+ri] + trS*V[128+ri] + xx*V[0+ri];
                        out[n] = v * gi * V[V_GZ+j];
                    }
                    *(float4*)&Szsh[ri*TS+tb]   = make_float4(out[0],out[1],out[2],out[3]);
                    *(float4*)&Szsh[ri*TS+tb+4] = make_float4(out[4],out[5],out[6],out[7]);
                }
            }
            __syncthreads();                       // S2 (Wr staged)
            // R gate
            g_stage1s(Ssh, Wb, Tsh, rg, cg, c64);
            BAR_GEMM();
            g_stage2(Wb, Tsh, acc, rg, cg);
            __syncthreads();                       // S3 (Wb free for Wh)
            {
                const float pp = scal[1], trS = scal[2], xx = scal[0];
                #pragma unroll
                for (int m=0;m<4;m++){
                    const int ri = ib+m;
                    const float gi  = V[V_GR+ri];
                    const float mi  = V[V_MU+ri];
                    const float rvi = V[V_R+ri];
                    float o[8], out[8];
                    #pragma unroll
                    for (int q=0;q<4;q++) unpack2(acc[m][q], o[2*q], o[2*q+1]);
                    const float4 spA = *(const float4*)&Ssh[ri*SP+jbg];
                    const float4 spB = *(const float4*)&Ssh[ri*SP+jbg+4];
                    const float sp8[8] = {spA.x,spA.y,spA.z,spA.w,spB.x,spB.y,spB.z,spB.w};
                    #pragma unroll
                    for (int n=0;n<8;n++){
                        const int j = jbg+n;
                        float v = o[n];
                        if (ri==j) v += pp*V[384+ri] + trS*V[384+ri] + xx*V[256+ri];
                        const float sr_ = v * gi * V[V_GR+j];
                        const float sp_ = sp8[n];
                        out[n] = sp_*sr_ + mi*V[V_MU+j]*sr_ + rvi*V[V_R+j]*sp_;
                    }
                    *(float4*)&Sgb[ri*NN+jbg]   = make_float4(out[0],out[1],out[2],out[3]);
                    *(float4*)&Sgb[ri*NN+jbg+4] = make_float4(out[4],out[5],out[6],out[7]);
                }
            }
            __threadfence();
            CLUSTER_SYNC();                        // S4
            // H gate
            g_stage1g(Sgb, Wb, Tsh, rg, cg, c64);
            BAR_GEMM();
            g_stage2(Wb, Tsh, acc, rg, cg);
            __syncthreads();                       // S5 (trg ready; Wb free for Wz)
            {
                float* outS = out_S + (size_t)(b*TT+st)*NN*NN;
                const float rr = scal[3], trg = scal[4], xx = scal[0];
                #pragma unroll
                for (int m=0;m<4;m++){
                    const int ri = ib+m;
                    const float gi = V[V_GH+ri];
                    const float zi = V[V_Z+ri], mi = V[V_MU+ri], hi = V[V_H+ri];
                    float o[8], sb8[8];
                    #pragma unroll
                    for (int q=0;q<4;q++) unpack2(acc[m][q], o[2*q], o[2*q+1]);
                    const float4 szA = *(const float4*)&Szsh[ri*TS+tb];
                    const float4 szB = *(const float4*)&Szsh[ri*TS+tb+4];
                    const float sz8[8] = {szA.x,szA.y,szA.z,szA.w,szB.x,szB.y,szB.z,szB.w};
                    const float4 spA = *(const float4*)&Ssh[ri*SP+jbg];
                    const float4 spB = *(const float4*)&Ssh[ri*SP+jbg+4];
                    const float sp8[8] = {spA.x,spA.y,spA.z,spA.w,spB.x,spB.y,spB.z,spB.w};
                    #pragma unroll
                    for (int n=0;n<8;n++){
                        const int j = jbg+n;
                        float v = o[n];
                        if (ri==j) v += rr*V[640+ri] + trg*V[640+ri] + xx*V[512+ri];
                        const float sh_ = v * gi * V[V_GH+j];
                        const float zj = V[V_Z+j], mj = V[V_MU+j], hj = V[V_H+j];
                        const float sz_ = sz8[n];
                        const float sp_ = sp8[n];
                        const float sa = sz_*sp_ + zi*zj*sp_ + mi*mj*sz_;
                        const float sb = sz_*sh_ + (1.f-zi)*(1.f-zj)*sh_ + hi*hj*sz_;
                        float s = sa + sb - sz_*mi*hj - sz_*hi*mj;
                        if (!isfinite(s)) s = 0.f;
                        if (ri==j) s = fabsf(s);
                        sb8[n] = s;
                    }
                    *(float4*)&outS[ri*NN+jbg]   = make_float4(sb8[0],sb8[1],sb8[2],sb8[3]);
                    *(float4*)&outS[ri*NN+jbg+4] = make_float4(sb8[4],sb8[5],sb8[6],sb8[7]);
                    *(float4*)&Ssh[ri*SP+jbg]    = make_float4(sb8[0],sb8[1],sb8[2],sb8[3]);
                    *(float4*)&Ssh[ri*SP+jbg+4]  = make_float4(sb8[4],sb8[5],sb8[6],sb8[7]);
                    #pragma unroll
                    for (int q=0;q<4;q++){
                        const u64t pv = pack2(sb8[2*q], sb8[2*q+1]);
                        const uint32_t la = ssh_u32 + (uint32_t)((ri*SP + jbg + 2*q)*4);
                        st_peer64(la, peer, pv);
                    }
                }
            }
            CLUSTER_SYNC();                        // S6
        }

        // ==== common tail (all 384 threads) ====
        if (st == 0){
            for (int e = tid; e < NN*NN; e += NTHREADS){
                const int row = e >> 7, col = e & 127;
                Ssh[row*SP+col] = Ssh[row*SP+col] * (1.0f + EPS_KICK);
            }
        }
        if (tid < 128) V[V_MU+tid] = V[V_MUN+tid];
        __syncthreads();                           // S7 (step end)
    }
}

extern "C" void kernel_launch(void* const* d_in, const int* in_sizes, int n_in,
                              void* d_out, int out_size)
{
    const float* x   = (const float*)d_in[0];
    const float* Uz  = (const float*)d_in[1];
    const float* Wz  = (const float*)d_in[2];
    const float* Ur  = (const float*)d_in[3];
    const float* Wr  = (const float*)d_in[4];
    const float* Uh  = (const float*)d_in[5];
    const float* Wh  = (const float*)d_in[6];
    const float* suz = (const float*)d_in[7];
    const float* swz = (const float*)d_in[8];
    const float* sur = (const float*)d_in[9];
    const float* swr = (const float*)d_in[10];
    const float* suh = (const float*)d_in[11];
    const float* swh = (const float*)d_in[12];

    float* out_mu = (float*)d_out;               // [B,T,N]
    float* out_S  = out_mu + (size_t)BB*TT*NN;   // [B,T,N,N]

    const size_t smem = ((size_t)SP*NN + (size_t)NN*TS + (size_t)NN*NN + (size_t)NN*TS)
                        * sizeof(float);         // 202,752 B
    cudaFuncSetAttribute(gru_kernel,
                         cudaFuncAttributeMaxDynamicSharedMemorySize, (int)smem);
    gru_kernel<<<BB*2, NTHREADS, smem>>>(x, Uz, Wz, Ur, Wr, Uh, Wh,
                                         suz, swz, sur, swr, suh, swh,
                                         out_mu, out_S);
}

// round 16
// speedup vs baseline: 1.1427x; 1.1427x over previous
#include <cuda_runtime.h>
#include <math.h>
#include <cstdint>

#define BB 64
#define TT 32
#define DD 128
#define NN 128
#define SP 132   // carry row stride (floats)
#define TS 68    // T / Sz row stride (floats)
#define NTHREADS 256

static __device__ float g_Sg[BB*NN*NN];

typedef unsigned long long u64t;

__device__ __forceinline__ float sigm(float x){ return 1.0f/(1.0f+expf(-x)); }
__device__ __forceinline__ float softplus_(float x){ return fmaxf(x,0.0f) + log1pf(expf(-fabsf(x))); }

__device__ __forceinline__ u64t pack2(float a, float b){
    u64t r; asm("mov.b64 %0, {%1,%2};" : "=l"(r) : "f"(a), "f"(b)); return r;
}
__device__ __forceinline__ void unpack2(u64t p, float& a, float& b){
    asm("mov.b64 {%0,%1}, %2;" : "=f"(a), "=f"(b) : "l"(p));
}
__device__ __forceinline__ u64t fma2_(u64t a, u64t b, u64t c){
    u64t d; asm("fma.rn.f32x2 %0, %1, %2, %3;" : "=l"(d) : "l"(a), "l"(b), "l"(c)); return d;
}
__device__ __forceinline__ uint32_t smem_u32(const void* p){
    uint32_t a;
    asm("{ .reg .u64 t; cvta.to.shared.u64 t, %1; cvt.u32.u64 %0, t; }" : "=r"(a) : "l"(p));
    return a;
}
__device__ __forceinline__ void st_peer64(uint32_t laddr, uint32_t peer, u64t v){
    uint32_t r;
    asm("mapa.shared::cluster.u32 %0, %1, %2;" : "=r"(r) : "r"(laddr), "r"(peer));
    asm volatile("st.shared::cluster.b64 [%0], %1;" :: "r"(r), "l"(v));
}
__device__ __forceinline__ void cp16(uint32_t smem_addr, const void* g){
    asm volatile("cp.async.cg.shared.global [%0], [%1], 16;" :: "r"(smem_addr), "l"(g));
}
#define CP_COMMIT() asm volatile("cp.async.commit_group;" ::: "memory")
#define CP_WAIT0()  asm volatile("cp.async.wait_group 0;"  ::: "memory")
#define CLUSTER_SYNC() do { \
    asm volatile("barrier.cluster.arrive.aligned;" ::: "memory"); \
    asm volatile("barrier.cluster.wait.aligned;"  ::: "memory"); \
} while(0)
#define BAR_GEMM() asm volatile("bar.sync 1, 128;" ::: "memory")
#define BAR_AUX()  asm volatile("bar.sync 2, 128;" ::: "memory")

// V layout (float offsets in static smem)
#define V_MU   768
#define V_Z    896
#define V_R    1024
#define V_H    1152
#define V_GZ   1280
#define V_GR   1408
#define V_GH   1536
#define V_RH   1664
#define V_XT   1792
#define V_MUN  1920
#define V_SCAL 2048
#define V_SIZE 2064

#define EPS_KICK 1.999936e-5f

// GEMM stage 1 (smem X): T[i,jl] = sum_l X[i*SP+l]*Wb[l*NN + jbg+jl]; 8 rows x 8 cols.
__device__ __forceinline__ void g_stage1s(const float* __restrict__ X,
                                          const float* __restrict__ Wb,
                                          float* __restrict__ Tsh,
                                          int rg, int cg, int c64)
{
    u64t acc[8][4];
    #pragma unroll
    for (int m=0;m<8;m++)
        #pragma unroll
        for (int q=0;q<4;q++) acc[m][q]=0ull;
    const int jbg = c64 + cg*8;
    #pragma unroll 2
    for (int l4=0; l4<NN; l4+=4){
        float4 s4[8];
        #pragma unroll
        for (int m=0;m<8;m++)
            s4[m] = *(const float4*)&X[(size_t)(rg*8+m)*SP + l4];
        #pragma unroll
        for (int c=0;c<4;c++){
            const float4 wA = *(const float4*)&Wb[(l4+c)*NN + jbg];
            const float4 wB = *(const float4*)&Wb[(l4+c)*NN + jbg + 4];
            u64t w[4];
            w[0]=pack2(wA.x,wA.y); w[1]=pack2(wA.z,wA.w);
            w[2]=pack2(wB.x,wB.y); w[3]=pack2(wB.z,wB.w);
            #pragma unroll
            for (int m=0;m<8;m++){
                const float s = (c==0)?s4[m].x:(c==1)?s4[m].y:(c==2)?s4[m].z:s4[m].w;
                const u64t s2 = pack2(s,s);
                #pragma unroll
                for (int q=0;q<4;q++) acc[m][q] = fma2_(s2, w[q], acc[m][q]);
            }
        }
    }
    const int tb = cg*8;
    #pragma unroll
    for (int m=0;m<8;m++)
        #pragma unroll
        for (int q=0;q<4;q++)
            *(u64t*)&Tsh[(rg*8+m)*TS + tb + 2*q] = acc[m][q];
}

// GEMM stage 1 (global X, stride NN), double-buffered prefetch.
__device__ __forceinline__ void g_stage1g(const float* __restrict__ Xg,
                                          const float* __restrict__ Wb,
                                          float* __restrict__ Tsh,
                                          int rg, int cg, int c64)
{
    u64t acc[8][4];
    #pragma unroll
    for (int m=0;m<8;m++)
        #pragma unroll
        for (int q=0;q<4;q++) acc[m][q]=0ull;
    const int jbg = c64 + cg*8;
    float4 cur[8], nxt[8];
    #pragma unroll
    for (int m=0;m<8;m++)
        cur[m] = __ldcg((const float4*)&Xg[(size_t)(rg*8+m)*NN]);
    for (int l4=0; l4<NN; l4+=4){
        if (l4 < NN-4){
            #pragma unroll
            for (int m=0;m<8;m++)
                nxt[m] = __ldcg((const float4*)&Xg[(size_t)(rg*8+m)*NN + l4 + 4]);
        }
        #pragma unroll
        for (int c=0;c<4;c++){
            const float4 wA = *(const float4*)&Wb[(l4+c)*NN + jbg];
            const float4 wB = *(const float4*)&Wb[(l4+c)*NN + jbg + 4];
            u64t w[4];
            w[0]=pack2(wA.x,wA.y); w[1]=pack2(wA.z,wA.w);
            w[2]=pack2(wB.x,wB.y); w[3]=pack2(wB.z,wB.w);
            #pragma unroll
            for (int m=0;m<8;m++){
                const float s = (c==0)?cur[m].x:(c==1)?cur[m].y:(c==2)?cur[m].z:cur[m].w;
                const u64t s2 = pack2(s,s);
                #pragma unroll
                for (int q=0;q<4;q++) acc[m][q] = fma2_(s2, w[q], acc[m][q]);
            }
        }
        #pragma unroll
        for (int m=0;m<8;m++) cur[m] = nxt[m];
    }
    const int tb = cg*8;
    #pragma unroll
    for (int m=0;m<8;m++)
        #pragma unroll
        for (int q=0;q<4;q++)
            *(u64t*)&Tsh[(rg*8+m)*TS + tb + 2*q] = acc[m][q];
}

// GEMM stage 2: acc[m][..] = sum_k Wb[k*NN + ib+m] * Tsh[k, jl..]
__device__ __forceinline__ void g_stage2(const float* __restrict__ Wb,
                                         const float* __restrict__ Tsh,
                                         u64t acc[8][4], int rg, int cg)
{
    #pragma unroll
    for (int m=0;m<8;m++)
        #pragma unroll
        for (int q=0;q<4;q++) acc[m][q]=0ull;
    const int tb = cg*8, ib = rg*8;
    #pragma unroll 2
    for (int k=0;k<NN;k++){
        const float4 tA = *(const float4*)&Tsh[k*TS + tb];
        const float4 tB = *(const float4*)&Tsh[k*TS + tb + 4];
        u64t t[4];
        t[0]=pack2(tA.x,tA.y); t[1]=pack2(tA.z,tA.w);
        t[2]=pack2(tB.x,tB.y); t[3]=pack2(tB.z,tB.w);
        const float4 wa = *(const float4*)&Wb[k*NN + ib];
        const float4 wb = *(const float4*)&Wb[k*NN + ib + 4];
        #pragma unroll
        for (int m=0;m<8;m++){
            const float wm = (m==0)?wa.x:(m==1)?wa.y:(m==2)?wa.z:(m==3)?wa.w
                           :(m==4)?wb.x:(m==5)?wb.y:(m==6)?wb.z:wb.w;
            const u64t w2 = pack2(wm, wm);
            #pragma unroll
            for (int q=0;q<4;q++) acc[m][q] = fma2_(w2, t[q], acc[m][q]);
        }
    }
}

__global__ void __launch_bounds__(NTHREADS,1) __cluster_dims__(2,1,1)
gru_kernel(const float* __restrict__ x,
           const float* __restrict__ Uz, const float* __restrict__ Wz,
           const float* __restrict__ Ur, const float* __restrict__ Wr,
           const float* __restrict__ Uh, const float* __restrict__ Wh,
           const float* __restrict__ suz, const float* __restrict__ swz,
           const float* __restrict__ sur, const float* __restrict__ swr,
           const float* __restrict__ suh, const float* __restrict__ swh,
           float* __restrict__ out_mu, float* __restrict__ out_S)
{
    extern __shared__ float sm[];
    float* Ssh  = sm;               // SP*NN : FULL carry S_p (replicated per CTA)
    float* Tsh  = Ssh + SP*NN;      // NN*TS : sandwich intermediate (own cols)
    float* Wb   = Tsh + NN*TS;      // NN*NN : staged W (full)
    float* Szsh = Wb  + NN*NN;      // NN*TS : S_z (own cols)
    __shared__ float V[V_SIZE];
    float* scal = V + V_SCAL;

    const int tid = threadIdx.x;
    const int b   = blockIdx.x >> 1;
    uint32_t rank; asm("mov.u32 %0, %%cluster_ctarank;" : "=r"(rank));
    const uint32_t peer = rank ^ 1u;
    const int c64 = (int)rank * 64;

    const bool is_gemm = (tid >= 128);
    const int wg = tid - 128;        // GEMM-local id 0..127
    const int rg = wg >> 3;          // 0..15 : rows rg*8..+7
    const int cg = wg & 7;           // 0..7  : local cols cg*8..+7
    const int ib = rg*8;
    const int jbg = c64 + cg*8;
    const int tb  = cg*8;

    const uint32_t ssh_u32 = smem_u32(Ssh);
    const uint32_t wb_u32  = smem_u32(Wb);

    float* Sgb = g_Sg + (size_t)b*NN*NN;

    for (int e = tid; e < SP*NN; e += NTHREADS) Ssh[e] = 0.f;
    if (tid < 128){
        V[tid]      = softplus_(suz[tid]);
        V[128+tid]  = softplus_(swz[tid]);
        V[256+tid]  = softplus_(sur[tid]);
        V[384+tid]  = softplus_(swr[tid]);
        V[512+tid]  = softplus_(suh[tid]);
        V[640+tid]  = softplus_(swh[tid]);
        V[V_MU+tid] = 0.f;
    }
    // initial Wz staging (all threads)
    for (int idx=tid; idx<4096; idx+=NTHREADS)
        cp16(wb_u32 + (uint32_t)idx*16, (const char*)Wz + (size_t)idx*16);
    CP_COMMIT(); CP_WAIT0();
    __syncthreads();

    for (int st = 0; st < TT; st++){
        if (!is_gemm){
            // ================= AUX warps (0-3) =================
            V[V_XT+tid] = x[(size_t)(b*TT+st)*DD + tid];
            BAR_AUX();
            // matvec z (verbatim chain)
            {
                const int j = tid; float acc = 0.f;
                #pragma unroll 32
                for (int d=0; d<DD; d++) acc += V[V_XT+d]*Uz[d*NN+j];
                #pragma unroll 32
                for (int k=0; k<NN; k++) acc += V[V_MU+k]*Wz[k*NN+j];
                const float z_ = sigm(acc);
                V[V_Z+j]  = z_;
                V[V_GZ+j] = z_*(1.f-z_);
            }
            // matvec r (verbatim chain)
            {
                const int j = tid; float acc = 0.f;
                #pragma unroll 32
                for (int d=0; d<DD; d++) acc += V[V_XT+d]*Ur[d*NN+j];
                #pragma unroll 32
                for (int k=0; k<NN; k++) acc += V[V_MU+k]*Wr[k*NN+j];
                const float r_ = sigm(acc);
                V[V_R+j]  = r_;
                V[V_GR+j] = r_*(1.f-r_);
                V[V_RH+j] = V[V_MU+j]*r_;
            }
            BAR_AUX();
            // scalar chains on 4 lanes (verbatim, branch-free trick for trS)
            if (tid < 4){
                const int which = tid;   // 0:xx 1:pp 2:trS 3:rr
                const float* src = (which==0) ? &V[V_XT] : (which==1) ? &V[V_MU]
                                 : (which==2) ? &Ssh[0]  : &V[V_RH];
                const int stride = (which==2) ? (SP+1) : 1;
                float a = 0.f;
                for (int k=0;k<NN;k++){
                    const float v = src[k*stride];
                    const float m2 = (which==2) ? 1.0f : v;
                    a += v * m2;
                }
                scal[which] = a;
            }
            // matvec h (verbatim chain)
            {
                const int j = tid; float acc = 0.f;
                #pragma unroll 32
                for (int d=0; d<DD; d++) acc += V[V_XT+d]*Uh[d*NN+j];
                #pragma unroll 32
                for (int k=0; k<NN; k++) acc += V[V_RH+k]*Wh[k*NN+j];
                const float h_ = tanhf(acc);
                V[V_H+j]  = h_;
                V[V_GH+j] = 1.f - h_*h_;
                const float mn = V[V_Z+j]*V[V_MU+j] + (1.f-V[V_Z+j])*h_;
                V[V_MUN+j] = mn;
                if (rank == 0) out_mu[(size_t)(b*TT+st)*NN + j] = mn;
            }
            __syncthreads();                       // S1
            // stage Wr while GEMM does z-epilogue
            for (int idx=tid; idx<4096; idx+=128)
                cp16(wb_u32 + (uint32_t)idx*16, (const char*)Wr + (size_t)idx*16);
            CP_COMMIT(); CP_WAIT0();
            __syncthreads();                       // S2
            // (GEMM: r-stage1 + r-stage2)
            __syncthreads();                       // S3
            // stage Wh while GEMM does r-epilogue
            for (int idx=tid; idx<4096; idx+=128)
                cp16(wb_u32 + (uint32_t)idx*16, (const char*)Wh + (size_t)idx*16);
            CP_COMMIT(); CP_WAIT0();
            CLUSTER_SYNC();                        // S4: Sg halves visible
            // trg serial chain (thread 0, pipelined loads; verbatim order)
            if (tid == 0){
                float tg=0.f;
                float va[8], vb[8];
                #pragma unroll
                for (int i=0;i<8;i++) va[i] = __ldcg(&Sgb[i*NN+i]);
                for (int g=0; g<16; g++){
                    if (g < 15){
                        #pragma unroll
                        for (int i=0;i<8;i++){
                            const int k = (g+1)*8 + i;
                            vb[i] = __ldcg(&Sgb[k*NN+k]);
                        }
                    }
                    #pragma unroll
                    for (int i=0;i<8;i++) tg += va[i];
                    #pragma unroll
                    for (int i=0;i<8;i++) va[i] = vb[i];
                }
                scal[4]=tg;
            }
            __syncthreads();                       // S5 (after GEMM h-stage2)
            // stage Wz for NEXT step while GEMM does h-epilogue
            for (int idx=tid; idx<4096; idx+=128)
                cp16(wb_u32 + (uint32_t)idx*16, (const char*)Wz + (size_t)idx*16);
            CP_COMMIT(); CP_WAIT0();
            CLUSTER_SYNC();                        // S6: carry merged
        } else {
            // ================= GEMM warps (4-7) =================
            // Z gate
            g_stage1s(Ssh, Wb, Tsh, rg, cg, c64);
            BAR_GEMM();
            u64t acc[8][4];
            g_stage2(Wb, Tsh, acc, rg, cg);
            __syncthreads();                       // S1 (z/gz/scalars ready; Wb free)
            {
                const float pp = scal[1], trS = scal[2], xx = scal[0];
                #pragma unroll
                for (int m=0;m<8;m++){
                    const int ri = ib+m;
                    const float gi = V[V_GZ+ri];
                    float o[8], out[8];
                    #pragma unroll
                    for (int q=0;q<4;q++) unpack2(acc[m][q], o[2*q], o[2*q+1]);
                    #pragma unroll
                    for (int n=0;n<8;n++){
                        const int j = jbg+n;
                        float v = o[n];
                        if (ri==j) v += pp*V[128+ri] + trS*V[128+ri] + xx*V[0+ri];
                        out[n] = v * gi * V[V_GZ+j];
                    }
                    *(float4*)&Szsh[ri*TS+tb]   = make_float4(out[0],out[1],out[2],out[3]);
                    *(float4*)&Szsh[ri*TS+tb+4] = make_float4(out[4],out[5],out[6],out[7]);
                }
            }
            __syncthreads();                       // S2 (Wr staged)
            // R gate
            g_stage1s(Ssh, Wb, Tsh, rg, cg, c64);
            BAR_GEMM();
            g_stage2(Wb, Tsh, acc, rg, cg);
            __syncthreads();                       // S3 (Wb free for Wh)
            {
                const float pp = scal[1], trS = scal[2], xx = scal[0];
                #pragma unroll
                for (int m=0;m<8;m++){
                    const int ri = ib+m;
                    const float gi  = V[V_GR+ri];
                    const float mi  = V[V_MU+ri];
                    const float rvi = V[V_R+ri];
                    float o[8], out[8];
                    #pragma unroll
                    for (int q=0;q<4;q++) unpack2(acc[m][q], o[2*q], o[2*q+1]);
                    const float4 spA = *(const float4*)&Ssh[ri*SP+jbg];
                    const float4 spB = *(const float4*)&Ssh[ri*SP+jbg+4];
                    const float sp8[8] = {spA.x,spA.y,spA.z,spA.w,spB.x,spB.y,spB.z,spB.w};
                    #pragma unroll
                    for (int n=0;n<8;n++){
                        const int j = jbg+n;
                        float v = o[n];
                        if (ri==j) v += pp*V[384+ri] + trS*V[384+ri] + xx*V[256+ri];
                        const float sr_ = v * gi * V[V_GR+j];
                        const float sp_ = sp8[n];
                        out[n] = sp_*sr_ + mi*V[V_MU+j]*sr_ + rvi*V[V_R+j]*sp_;
                    }
                    *(float4*)&Sgb[ri*NN+jbg]   = make_float4(out[0],out[1],out[2],out[3]);
                    *(float4*)&Sgb[ri*NN+jbg+4] = make_float4(out[4],out[5],out[6],out[7]);
                }
            }
            __threadfence();
            CLUSTER_SYNC();                        // S4
            // H gate
            g_stage1g(Sgb, Wb, Tsh, rg, cg, c64);
            BAR_GEMM();
            g_stage2(Wb, Tsh, acc, rg, cg);
            __syncthreads();                       // S5 (trg ready; Wb free for Wz)
            {
                float* outS = out_S + (size_t)(b*TT+st)*NN*NN;
                const float rr = scal[3], trg = scal[4], xx = scal[0];
                #pragma unroll
                for (int m=0;m<8;m++){
                    const int ri = ib+m;
                    const float gi = V[V_GH+ri];
                    const float zi = V[V_Z+ri], mi = V[V_MU+ri], hi = V[V_H+ri];
                    float o[8], sb8[8];
                    #pragma unroll
                    for (int q=0;q<4;q++) unpack2(acc[m][q], o[2*q], o[2*q+1]);
                    const float4 szA = *(const float4*)&Szsh[ri*TS+tb];
                    const float4 szB = *(const float4*)&Szsh[ri*TS+tb+4];
                    const float sz8[8] = {szA.x,szA.y,szA.z,szA.w,szB.x,szB.y,szB.z,szB.w};
                    const float4 spA = *(const float4*)&Ssh[ri*SP+jbg];
                    const float4 spB = *(const float4*)&Ssh[ri*SP+jbg+4];
                    const float sp8[8] = {spA.x,spA.y,spA.z,spA.w,spB.x,spB.y,spB.z,spB.w};
                    #pragma unroll
                    for (int n=0;n<8;n++){
                        const int j = jbg+n;
                        float v = o[n];
                        if (ri==j) v += rr*V[640+ri] + trg*V[640+ri] + xx*V[512+ri];
                        const float sh_ = v * gi * V[V_GH+j];
                        const float zj = V[V_Z+j], mj = V[V_MU+j], hj = V[V_H+j];
                        const float sz_ = sz8[n];
                        const float sp_ = sp8[n];
                        const float sa = sz_*sp_ + zi*zj*sp_ + mi*mj*sz_;
                        const float sb = sz_*sh_ + (1.f-zi)*(1.f-zj)*sh_ + hi*hj*sz_;
                        float s = sa + sb - sz_*mi*hj - sz_*hi*mj;
                        if (!isfinite(s)) s = 0.f;
                        if (ri==j) s = fabsf(s);
                        sb8[n] = s;
                    }
                    *(float4*)&outS[ri*NN+jbg]   = make_float4(sb8[0],sb8[1],sb8[2],sb8[3]);
                    *(float4*)&outS[ri*NN+jbg+4] = make_float4(sb8[4],sb8[5],sb8[6],sb8[7]);
                    *(float4*)&Ssh[ri*SP+jbg]    = make_float4(sb8[0],sb8[1],sb8[2],sb8[3]);
                    *(float4*)&Ssh[ri*SP+jbg+4]  = make_float4(sb8[4],sb8[5],sb8[6],sb8[7]);
                    #pragma unroll
                    for (int q=0;q<4;q++){
                        const u64t pv = pack2(sb8[2*q], sb8[2*q+1]);
                        const uint32_t la = ssh_u32 + (uint32_t)((ri*SP + jbg + 2*q)*4);
                        st_peer64(la, peer, pv);
                    }
                }
            }
            CLUSTER_SYNC();                        // S6
        }

        // ==== common tail (barrier only at st==0; ordering audit in theory) ====
        if (st == 0){
            for (int e = tid; e < NN*NN; e += NTHREADS){
                const int row = e >> 7, col = e & 127;
                Ssh[row*SP+col] = Ssh[row*SP+col] * (1.0f + EPS_KICK);
            }
            __syncthreads();
        }
        if (tid < 128) V[V_MU+tid] = V[V_MUN+tid];
        // no per-step tail barrier: V_MU write->read ordered by BAR_AUX / S1;
        // Ssh carry ordered by CLUSTER_SYNC S6.
    }
}

extern "C" void kernel_launch(void* const* d_in, const int* in_sizes, int n_in,
                              void* d_out, int out_size)
{
    const float* x   = (const float*)d_in[0];
    const float* Uz  = (const float*)d_in[1];
    const float* Wz  = (const float*)d_in[2];
    const float* Ur  = (const float*)d_in[3];
    const float* Wr  = (const float*)d_in[4];
    const float* Uh  = (const float*)d_in[5];
    const float* Wh  = (const float*)d_in[6];
    const float* suz = (const float*)d_in[7];
    const float* swz = (const float*)d_in[8];
    const float* sur = (const float*)d_in[9];
    const float* swr = (const float*)d_in[10];
    const float* suh = (const float*)d_in[11];
    const float* swh = (const float*)d_in[12];

    float* out_mu = (float*)d_out;               // [B,T,N]
    float* out_S  = out_mu + (size_t)BB*TT*NN;   // [B,T,N,N]

    const size_t smem = ((size_t)SP*NN + (size_t)NN*TS + (size_t)NN*NN + (size_t)NN*TS)
                        * sizeof(float);         // 202,752 B
    cudaFuncSetAttribute(gru_kernel,
                         cudaFuncAttributeMaxDynamicSharedMemorySize, (int)smem);
    gru_kernel<<<BB*2, NTHREADS, smem>>>(x, Uz, Wz, Ur, Wr, Uh, Wh,
                                         suz, swz, sur, swr, suh, swh,
                                         out_mu, out_S);
}

// round 17
// speedup vs baseline: 1.2464x; 1.0907x over previous
#include <cuda_runtime.h>
#include <math.h>
#include <cstdint>

#define BB 64
#define TT 32
#define DD 128
#define NN 128
#define SP 132   // carry row stride (floats)
#define TS 68    // T / Sz row stride (floats)
#define NTHREADS 256

static __device__ float g_Sg[BB*NN*NN];

typedef unsigned long long u64t;

__device__ __forceinline__ float sigm(float x){ return 1.0f/(1.0f+expf(-x)); }
__device__ __forceinline__ float softplus_(float x){ return fmaxf(x,0.0f) + log1pf(expf(-fabsf(x))); }

__device__ __forceinline__ u64t pack2(float a, float b){
    u64t r; asm("mov.b64 %0, {%1,%2};" : "=l"(r) : "f"(a), "f"(b)); return r;
}
__device__ __forceinline__ void unpack2(u64t p, float& a, float& b){
    asm("mov.b64 {%0,%1}, %2;" : "=f"(a), "=f"(b) : "l"(p));
}
__device__ __forceinline__ u64t fma2_(u64t a, u64t b, u64t c){
    u64t d; asm("fma.rn.f32x2 %0, %1, %2, %3;" : "=l"(d) : "l"(a), "l"(b), "l"(c)); return d;
}
__device__ __forceinline__ uint32_t smem_u32(const void* p){
    uint32_t a;
    asm("{ .reg .u64 t; cvta.to.shared.u64 t, %1; cvt.u32.u64 %0, t; }" : "=r"(a) : "l"(p));
    return a;
}
__device__ __forceinline__ void st_peer64(uint32_t laddr, uint32_t peer, u64t v){
    uint32_t r;
    asm("mapa.shared::cluster.u32 %0, %1, %2;" : "=r"(r) : "r"(laddr), "r"(peer));
    asm volatile("st.shared::cluster.b64 [%0], %1;" :: "r"(r), "l"(v));
}
__device__ __forceinline__ void cp16(uint32_t smem_addr, const void* g){
    asm volatile("cp.async.cg.shared.global [%0], [%1], 16;" :: "r"(smem_addr), "l"(g));
}
__device__ __forceinline__ void stcs4(float* p, float4 v){
    __stcs((float4*)p, v);
}
#define CP_COMMIT() asm volatile("cp.async.commit_group;" ::: "memory")
#define CP_WAIT0()  asm volatile("cp.async.wait_group 0;"  ::: "memory")
#define CLUSTER_SYNC() do { \
    asm volatile("barrier.cluster.arrive.aligned;" ::: "memory"); \
    asm volatile("barrier.cluster.wait.aligned;"  ::: "memory"); \
} while(0)
#define BAR_GEMM() asm volatile("bar.sync 1, 128;" ::: "memory")
#define BAR_AUX()  asm volatile("bar.sync 2, 128;" ::: "memory")

// V layout (float offsets in static smem)
#define V_MU   768
#define V_Z    896
#define V_R    1024
#define V_H    1152
#define V_GZ   1280
#define V_GR   1408
#define V_GH   1536
#define V_RH   1664
#define V_XT   1792
#define V_MUN  1920
#define V_SCAL 2048
#define V_SIZE 2064

#define EPS_KICK 1.999936e-5f

// GEMM stage 1 (smem X): T[i,jl] = sum_l X[i*SP+l]*Wb[l*NN + jbg+jl]; 8 rows x 8 cols.
__device__ __forceinline__ void g_stage1s(const float* __restrict__ X,
                                          const float* __restrict__ Wb,
                                          float* __restrict__ Tsh,
                                          int rg, int cg, int c64)
{
    u64t acc[8][4];
    #pragma unroll
    for (int m=0;m<8;m++)
        #pragma unroll
        for (int q=0;q<4;q++) acc[m][q]=0ull;
    const int jbg = c64 + cg*8;
    #pragma unroll 2
    for (int l4=0; l4<NN; l4+=4){
        float4 s4[8];
        #pragma unroll
        for (int m=0;m<8;m++)
            s4[m] = *(const float4*)&X[(size_t)(rg*8+m)*SP + l4];
        #pragma unroll
        for (int c=0;c<4;c++){
            const float4 wA = *(const float4*)&Wb[(l4+c)*NN + jbg];
            const float4 wB = *(const float4*)&Wb[(l4+c)*NN + jbg + 4];
            u64t w[4];
            w[0]=pack2(wA.x,wA.y); w[1]=pack2(wA.z,wA.w);
            w[2]=pack2(wB.x,wB.y); w[3]=pack2(wB.z,wB.w);
            #pragma unroll
            for (int m=0;m<8;m++){
                const float s = (c==0)?s4[m].x:(c==1)?s4[m].y:(c==2)?s4[m].z:s4[m].w;
                const u64t s2 = pack2(s,s);
                #pragma unroll
                for (int q=0;q<4;q++) acc[m][q] = fma2_(s2, w[q], acc[m][q]);
            }
        }
    }
    const int tb = cg*8;
    #pragma unroll
    for (int m=0;m<8;m++)
        #pragma unroll
        for (int q=0;q<4;q++)
            *(u64t*)&Tsh[(rg*8+m)*TS + tb + 2*q] = acc[m][q];
}

// GEMM stage 1 (global X, stride NN), double-buffered prefetch.
__device__ __forceinline__ void g_stage1g(const float* __restrict__ Xg,
                                          const float* __restrict__ Wb,
                                          float* __restrict__ Tsh,
                                          int rg, int cg, int c64)
{
    u64t acc[8][4];
    #pragma unroll
    for (int m=0;m<8;m++)
        #pragma unroll
        for (int q=0;q<4;q++) acc[m][q]=0ull;
    const int jbg = c64 + cg*8;
    float4 cur[8], nxt[8];
    #pragma unroll
    for (int m=0;m<8;m++)
        cur[m] = __ldcg((const float4*)&Xg[(size_t)(rg*8+m)*NN]);
    for (int l4=0; l4<NN; l4+=4){
        if (l4 < NN-4){
            #pragma unroll
            for (int m=0;m<8;m++)
                nxt[m] = __ldcg((const float4*)&Xg[(size_t)(rg*8+m)*NN + l4 + 4]);
        }
        #pragma unroll
        for (int c=0;c<4;c++){
            const float4 wA = *(const float4*)&Wb[(l4+c)*NN + jbg];
            const float4 wB = *(const float4*)&Wb[(l4+c)*NN + jbg + 4];
            u64t w[4];
            w[0]=pack2(wA.x,wA.y); w[1]=pack2(wA.z,wA.w);
            w[2]=pack2(wB.x,wB.y); w[3]=pack2(wB.z,wB.w);
            #pragma unroll
            for (int m=0;m<8;m++){
                const float s = (c==0)?cur[m].x:(c==1)?cur[m].y:(c==2)?cur[m].z:cur[m].w;
                const u64t s2 = pack2(s,s);
                #pragma unroll
                for (int q=0;q<4;q++) acc[m][q] = fma2_(s2, w[q], acc[m][q]);
            }
        }
        #pragma unroll
        for (int m=0;m<8;m++) cur[m] = nxt[m];
    }
    const int tb = cg*8;
    #pragma unroll
    for (int m=0;m<8;m++)
        #pragma unroll
        for (int q=0;q<4;q++)
            *(u64t*)&Tsh[(rg*8+m)*TS + tb + 2*q] = acc[m][q];
}

// GEMM stage 2: acc[m][..] = sum_k Wb[k*NN + ib+m] * Tsh[k, jl..]
__device__ __forceinline__ void g_stage2(const float* __restrict__ Wb,
                                         const float* __restrict__ Tsh,
                                         u64t acc[8][4], int rg, int cg)
{
    #pragma unroll
    for (int m=0;m<8;m++)
        #pragma unroll
        for (int q=0;q<4;q++) acc[m][q]=0ull;
    const int tb = cg*8, ib = rg*8;
    #pragma unroll 4
    for (int k=0;k<NN;k++){
        const float4 tA = *(const float4*)&Tsh[k*TS + tb];
        const float4 tB = *(const float4*)&Tsh[k*TS + tb + 4];
        u64t t[4];
        t[0]=pack2(tA.x,tA.y); t[1]=pack2(tA.z,tA.w);
        t[2]=pack2(tB.x,tB.y); t[3]=pack2(tB.z,tB.w);
        const float4 wa = *(const float4*)&Wb[k*NN + ib];
        const float4 wb = *(const float4*)&Wb[k*NN + ib + 4];
        #pragma unroll
        for (int m=0;m<8;m++){
            const float wm = (m==0)?wa.x:(m==1)?wa.y:(m==2)?wa.z:(m==3)?wa.w
                           :(m==4)?wb.x:(m==5)?wb.y:(m==6)?wb.z:wb.w;
            const u64t w2 = pack2(wm, wm);
            #pragma unroll
            for (int q=0;q<4;q++) acc[m][q] = fma2_(w2, t[q], acc[m][q]);
        }
    }
}

__global__ void __launch_bounds__(NTHREADS,1) __cluster_dims__(2,1,1)
gru_kernel(const float* __restrict__ x,
           const float* __restrict__ Uz, const float* __restrict__ Wz,
           const float* __restrict__ Ur, const float* __restrict__ Wr,
           const float* __restrict__ Uh, const float* __restrict__ Wh,
           const float* __restrict__ suz, const float* __restrict__ swz,
           const float* __restrict__ sur, const float* __restrict__ swr,
           const float* __restrict__ suh, const float* __restrict__ swh,
           float* __restrict__ out_mu, float* __restrict__ out_S)
{
    extern __shared__ float sm[];
    float* Ssh  = sm;               // SP*NN : FULL carry S_p (replicated per CTA)
    float* Tsh  = Ssh + SP*NN;      // NN*TS : sandwich intermediate (own cols)
    float* Wb   = Tsh + NN*TS;      // NN*NN : staged W (full)
    float* Szsh = Wb  + NN*NN;      // NN*TS : S_z (own cols)
    __shared__ float V[V_SIZE];
    float* scal = V + V_SCAL;

    const int tid = threadIdx.x;
    const int b   = blockIdx.x >> 1;
    uint32_t rank; asm("mov.u32 %0, %%cluster_ctarank;" : "=r"(rank));
    const uint32_t peer = rank ^ 1u;
    const int c64 = (int)rank * 64;

    const bool is_gemm = (tid >= 128);
    const int wg = tid - 128;        // GEMM-local id 0..127
    const int rg = wg >> 3;          // 0..15 : rows rg*8..+7
    const int cg = wg & 7;           // 0..7  : local cols cg*8..+7
    const int ib = rg*8;
    const int jbg = c64 + cg*8;
    const int tb  = cg*8;

    const uint32_t ssh_u32 = smem_u32(Ssh);
    const uint32_t wb_u32  = smem_u32(Wb);

    float* Sgb = g_Sg + (size_t)b*NN*NN;

    for (int e = tid; e < SP*NN; e += NTHREADS) Ssh[e] = 0.f;
    if (tid < 128){
        V[tid]      = softplus_(suz[tid]);
        V[128+tid]  = softplus_(swz[tid]);
        V[256+tid]  = softplus_(sur[tid]);
        V[384+tid]  = softplus_(swr[tid]);
        V[512+tid]  = softplus_(suh[tid]);
        V[640+tid]  = softplus_(swh[tid]);
        V[V_MU+tid] = 0.f;
    }
    // initial Wz staging (all threads)
    for (int idx=tid; idx<4096; idx+=NTHREADS)
        cp16(wb_u32 + (uint32_t)idx*16, (const char*)Wz + (size_t)idx*16);
    CP_COMMIT(); CP_WAIT0();
    __syncthreads();

    for (int st = 0; st < TT; st++){
        if (!is_gemm){
            // ================= AUX warps (0-3) =================
            V[V_XT+tid] = x[(size_t)(b*TT+st)*DD + tid];
            BAR_AUX();
            // matvec z (verbatim chain)
            {
                const int j = tid; float acc = 0.f;
                #pragma unroll 32
                for (int d=0; d<DD; d++) acc += V[V_XT+d]*Uz[d*NN+j];
                #pragma unroll 32
                for (int k=0; k<NN; k++) acc += V[V_MU+k]*Wz[k*NN+j];
                const float z_ = sigm(acc);
                V[V_Z+j]  = z_;
                V[V_GZ+j] = z_*(1.f-z_);
            }
            // matvec r (verbatim chain)
            {
                const int j = tid; float acc = 0.f;
                #pragma unroll 32
                for (int d=0; d<DD; d++) acc += V[V_XT+d]*Ur[d*NN+j];
                #pragma unroll 32
                for (int k=0; k<NN; k++) acc += V[V_MU+k]*Wr[k*NN+j];
                const float r_ = sigm(acc);
                V[V_R+j]  = r_;
                V[V_GR+j] = r_*(1.f-r_);
                V[V_RH+j] = V[V_MU+j]*r_;
            }
            BAR_AUX();
            // scalar chains on 4 lanes (verbatim, branch-free trick for trS)
            if (tid < 4){
                const int which = tid;   // 0:xx 1:pp 2:trS 3:rr
                const float* src = (which==0) ? &V[V_XT] : (which==1) ? &V[V_MU]
                                 : (which==2) ? &Ssh[0]  : &V[V_RH];
                const int stride = (which==2) ? (SP+1) : 1;
                float a = 0.f;
                for (int k=0;k<NN;k++){
                    const float v = src[k*stride];
                    const float m2 = (which==2) ? 1.0f : v;
                    a += v * m2;
                }
                scal[which] = a;
            }
            // matvec h (verbatim chain)
            {
                const int j = tid; float acc = 0.f;
                #pragma unroll 32
                for (int d=0; d<DD; d++) acc += V[V_XT+d]*Uh[d*NN+j];
                #pragma unroll 32
                for (int k=0; k<NN; k++) acc += V[V_RH+k]*Wh[k*NN+j];
                const float h_ = tanhf(acc);
                V[V_H+j]  = h_;
                V[V_GH+j] = 1.f - h_*h_;
                const float mn = V[V_Z+j]*V[V_MU+j] + (1.f-V[V_Z+j])*h_;
                V[V_MUN+j] = mn;
                if (rank == 0) out_mu[(size_t)(b*TT+st)*NN + j] = mn;
            }
            __syncthreads();                       // S1
            // stage Wr while GEMM does z-epilogue
            for (int idx=tid; idx<4096; idx+=128)
                cp16(wb_u32 + (uint32_t)idx*16, (const char*)Wr + (size_t)idx*16);
            CP_COMMIT(); CP_WAIT0();
            __syncthreads();                       // S2
            // (GEMM: r-stage1 + r-stage2)
            __syncthreads();                       // S3
            // stage Wh while GEMM does r-epilogue
            for (int idx=tid; idx<4096; idx+=128)
                cp16(wb_u32 + (uint32_t)idx*16, (const char*)Wh + (size_t)idx*16);
            CP_COMMIT(); CP_WAIT0();
            CLUSTER_SYNC();                        // S4: Sg halves visible
            // trg serial chain (thread 0, pipelined loads; verbatim order)
            if (tid == 0){
                float tg=0.f;
                float va[8], vb[8];
                #pragma unroll
                for (int i=0;i<8;i++) va[i] = __ldcg(&Sgb[i*NN+i]);
                for (int g=0; g<16; g++){
                    if (g < 15){
                        #pragma unroll
                        for (int i=0;i<8;i++){
                            const int k = (g+1)*8 + i;
                            vb[i] = __ldcg(&Sgb[k*NN+k]);
                        }
                    }
                    #pragma unroll
                    for (int i=0;i<8;i++) tg += va[i];
                    #pragma unroll
                    for (int i=0;i<8;i++) va[i] = vb[i];
                }
                scal[4]=tg;
            }
            __syncthreads();                       // S5 (after GEMM h-stage2)
            // stage Wz for NEXT step while GEMM does h-epilogue
            for (int idx=tid; idx<4096; idx+=128)
                cp16(wb_u32 + (uint32_t)idx*16, (const char*)Wz + (size_t)idx*16);
            CP_COMMIT(); CP_WAIT0();
            CLUSTER_SYNC();                        // S6: carry merged
        } else {
            // ================= GEMM warps (4-7) =================
            // Z gate
            g_stage1s(Ssh, Wb, Tsh, rg, cg, c64);
            BAR_GEMM();
            u64t acc[8][4];
            g_stage2(Wb, Tsh, acc, rg, cg);
            __syncthreads();                       // S1 (z/gz/scalars ready; Wb free)
            {
                const float pp = scal[1], trS = scal[2], xx = scal[0];
                #pragma unroll
                for (int m=0;m<8;m++){
                    const int ri = ib+m;
                    const float gi = V[V_GZ+ri];
                    float o[8], out[8];
                    #pragma unroll
                    for (int q=0;q<4;q++) unpack2(acc[m][q], o[2*q], o[2*q+1]);
                    #pragma unroll
                    for (int n=0;n<8;n++){
                        const int j = jbg+n;
                        float v = o[n];
                        if (ri==j) v += pp*V[128+ri] + trS*V[128+ri] + xx*V[0+ri];
                        out[n] = v * gi * V[V_GZ+j];
                    }
                    *(float4*)&Szsh[ri*TS+tb]   = make_float4(out[0],out[1],out[2],out[3]);
                    *(float4*)&Szsh[ri*TS+tb+4] = make_float4(out[4],out[5],out[6],out[7]);
                }
            }
            __syncthreads();                       // S2 (Wr staged)
            // R gate
            g_stage1s(Ssh, Wb, Tsh, rg, cg, c64);
            BAR_GEMM();
            g_stage2(Wb, Tsh, acc, rg, cg);
            __syncthreads();                       // S3 (Wb free for Wh)
            {
                const float pp = scal[1], trS = scal[2], xx = scal[0];
                #pragma unroll
                for (int m=0;m<8;m++){
                    const int ri = ib+m;
                    const float gi  = V[V_GR+ri];
                    const float mi  = V[V_MU+ri];
                    const float rvi = V[V_R+ri];
                    float o[8], out[8];
                    #pragma unroll
                    for (int q=0;q<4;q++) unpack2(acc[m][q], o[2*q], o[2*q+1]);
                    const float4 spA = *(const float4*)&Ssh[ri*SP+jbg];
                    const float4 spB = *(const float4*)&Ssh[ri*SP+jbg+4];
                    const float sp8[8] = {spA.x,spA.y,spA.z,spA.w,spB.x,spB.y,spB.z,spB.w};
                    #pragma unroll
                    for (int n=0;n<8;n++){
                        const int j = jbg+n;
                        float v = o[n];
                        if (ri==j) v += pp*V[384+ri] + trS*V[384+ri] + xx*V[256+ri];
                        const float sr_ = v * gi * V[V_GR+j];
                        const float sp_ = sp8[n];
                        out[n] = sp_*sr_ + mi*V[V_MU+j]*sr_ + rvi*V[V_R+j]*sp_;
                    }
                    *(float4*)&Sgb[ri*NN+jbg]   = make_float4(out[0],out[1],out[2],out[3]);
                    *(float4*)&Sgb[ri*NN+jbg+4] = make_float4(out[4],out[5],out[6],out[7]);
                }
            }
            __threadfence();
            CLUSTER_SYNC();                        // S4
            // H gate
            g_stage1g(Sgb, Wb, Tsh, rg, cg, c64);
            BAR_GEMM();
            g_stage2(Wb, Tsh, acc, rg, cg);
            __syncthreads();                       // S5 (trg ready; Wb free for Wz)
            {
                float* outS = out_S + (size_t)(b*TT+st)*NN*NN;
                const float rr = scal[3], trg = scal[4], xx = scal[0];
                #pragma unroll
                for (int m=0;m<8;m++){
                    const int ri = ib+m;
                    const float gi = V[V_GH+ri];
                    const float zi = V[V_Z+ri], mi = V[V_MU+ri], hi = V[V_H+ri];
                    float o[8], sb8[8];
                    #pragma unroll
                    for (int q=0;q<4;q++) unpack2(acc[m][q], o[2*q], o[2*q+1]);
                    const float4 szA = *(const float4*)&Szsh[ri*TS+tb];
                    const float4 szB = *(const float4*)&Szsh[ri*TS+tb+4];
                    const float sz8[8] = {szA.x,szA.y,szA.z,szA.w,szB.x,szB.y,szB.z,szB.w};
                    const float4 spA = *(const float4*)&Ssh[ri*SP+jbg];
                    const float4 spB = *(const float4*)&Ssh[ri*SP+jbg+4];
                    const float sp8[8] = {spA.x,spA.y,spA.z,spA.w,spB.x,spB.y,spB.z,spB.w};
                    #pragma unroll
                    for (int n=0;n<8;n++){
                        const int j = jbg+n;
                        float v = o[n];
                        if (ri==j) v += rr*V[640+ri] + trg*V[640+ri] + xx*V[512+ri];
                        const float sh_ = v * gi * V[V_GH+j];
                        const float zj = V[V_Z+j], mj = V[V_MU+j], hj = V[V_H+j];
                        const float sz_ = sz8[n];
                        const float sp_ = sp8[n];
                        const float sa = sz_*sp_ + zi*zj*sp_ + mi*mj*sz_;
                        const float sb = sz_*sh_ + (1.f-zi)*(1.f-zj)*sh_ + hi*hj*sz_;
                        float s = sa + sb - sz_*mi*hj - sz_*hi*mj;
                        if (!isfinite(s)) s = 0.f;
                        if (ri==j) s = fabsf(s);
                        sb8[n] = s;
                    }
                    // streaming stores: outS is write-once, keep it out of L2 hot set
                    stcs4(&outS[ri*NN+jbg],   make_float4(sb8[0],sb8[1],sb8[2],sb8[3]));
                    stcs4(&outS[ri*NN+jbg+4], make_float4(sb8[4],sb8[5],sb8[6],sb8[7]));
                    *(float4*)&Ssh[ri*SP+jbg]    = make_float4(sb8[0],sb8[1],sb8[2],sb8[3]);
                    *(float4*)&Ssh[ri*SP+jbg+4]  = make_float4(sb8[4],sb8[5],sb8[6],sb8[7]);
                    #pragma unroll
                    for (int q=0;q<4;q++){
                        const u64t pv = pack2(sb8[2*q], sb8[2*q+1]);
                        const uint32_t la = ssh_u32 + (uint32_t)((ri*SP + jbg + 2*q)*4);
                        st_peer64(la, peer, pv);
                    }
                }
            }
            CLUSTER_SYNC();                        // S6
        }

        // ==== common tail (barrier only at st==0) ====
        if (st == 0){
            for (int e = tid; e < NN*NN; e += NTHREADS){
                const int row = e >> 7, col = e & 127;
                Ssh[row*SP+col] = Ssh[row*SP+col] * (1.0f + EPS_KICK);
            }
            __syncthreads();
        }
        if (tid < 128) V[V_MU+tid] = V[V_MUN+tid];
        // no per-step tail barrier: V_MU write->read ordered by BAR_AUX / S1;
        // Ssh carry ordered by CLUSTER_SYNC S6.
    }
}

extern "C" void kernel_launch(void* const* d_in, const int* in_sizes, int n_in,
                              void* d_out, int out_size)
{
    const float* x   = (const float*)d_in[0];
    const float* Uz  = (const float*)d_in[1];
    const float* Wz  = (const float*)d_in[2];
    const float* Ur  = (const float*)d_in[3];
    const float* Wr  = (const float*)d_in[4];
    const float* Uh  = (const float*)d_in[5];
    const float* Wh  = (const float*)d_in[6];
    const float* suz = (const float*)d_in[7];
    const float* swz = (const float*)d_in[8];
    const float* sur = (const float*)d_in[9];
    const float* swr = (const float*)d_in[10];
    const float* suh = (const float*)d_in[11];
    const float* swh = (const float*)d_in[12];

    float* out_mu = (float*)d_out;               // [B,T,N]
    float* out_S  = out_mu + (size_t)BB*TT*NN;   // [B,T,N,N]

    const size_t smem = ((size_t)SP*NN + (size_t)NN*TS + (size_t)NN*NN + (size_t)NN*TS)
                        * sizeof(float);         // 202,752 B
    cudaFuncSetAttribute(gru_kernel,
                         cudaFuncAttributeMaxDynamicSharedMemorySize, (int)smem);
    gru_kernel<<<BB*2, NTHREADS, smem>>>(x, Uz, Wz, Ur, Wr, Uh, Wh,
                                         suz, swz, sur, swr, suh, swh,
                                         out_mu, out_S);
}